// round 5
// baseline (speedup 1.0000x reference)
#include <cuda_runtime.h>
#include <cstdint>
#include <cstddef>

// ---------------------------------------------------------------------------
// Bottleneck: BN -> conv1x1(1024->256) -> relu -> BN -> conv1x1(256->64)
//             -> split (mu, logvar)
// B=32, C=1024, T=2048. BN folded into GEMM weights. GEMMs in tf32 mma.sync.
// ---------------------------------------------------------------------------

#define EPSV 1e-5f
constexpr int Tdim = 2048;
constexpr int Bn   = 32;
constexpr int BN   = 128;   // t-tile
constexpr int BK   = 16;    // k-tile

// scratch (allocation-free rule: __device__ globals)
__device__ float g_h[(size_t)Bn * 256 * Tdim];       // 64 MiB intermediate
__device__ float g_s1[1024], g_t1[1024];
__device__ float g_w1f[256 * 1024];
__device__ float g_b1f[256];
__device__ float g_s2[256], g_t2[256];
__device__ float g_w2f[64 * 256];
__device__ float g_b2f[64];

__device__ __forceinline__ float to_tf32(float v) {
    uint32_t u;
    asm("cvt.rna.tf32.f32 %0, %1;" : "=r"(u) : "f"(v));
    return __uint_as_float(u);
}

__device__ __forceinline__ void mma8(float* c, const uint32_t* a, const uint32_t* b) {
    asm volatile(
        "mma.sync.aligned.m16n8k8.row.col.f32.tf32.tf32.f32 "
        "{%0,%1,%2,%3}, {%4,%5,%6,%7}, {%8,%9}, {%0,%1,%2,%3};"
        : "+f"(c[0]), "+f"(c[1]), "+f"(c[2]), "+f"(c[3])
        : "r"(a[0]), "r"(a[1]), "r"(a[2]), "r"(a[3]), "r"(b[0]), "r"(b[1]));
}

// ---------------------------------------------------------------------------
// Per-channel BN stats over (B, T): emits scale s = g*rsqrt(var+eps),
// shift t = b - mean*s.  x layout: [B][C][T].  grid = C blocks, 256 threads.
// ---------------------------------------------------------------------------
__global__ void bn_stats_kernel(const float* __restrict__ x,
                                const float* __restrict__ gamma,
                                const float* __restrict__ beta,
                                float* __restrict__ s_out,
                                float* __restrict__ t_out,
                                int C)
{
    const int c = blockIdx.x, tid = threadIdx.x;
    float s = 0.f, ss = 0.f;
    const size_t cstride = (size_t)C * Tdim;
    const float* base = x + (size_t)c * Tdim;
    for (int b = 0; b < Bn; ++b) {
        const float4* row = reinterpret_cast<const float4*>(base + (size_t)b * cstride);
#pragma unroll
        for (int i = 0; i < (Tdim / 4) / 256; ++i) {
            float4 v = row[tid + i * 256];
            s  += (v.x + v.y) + (v.z + v.w);
            ss += (v.x * v.x + v.y * v.y) + (v.z * v.z + v.w * v.w);
        }
    }
#pragma unroll
    for (int o = 16; o > 0; o >>= 1) {
        s  += __shfl_xor_sync(0xffffffffu, s, o);
        ss += __shfl_xor_sync(0xffffffffu, ss, o);
    }
    __shared__ float rs[8], rss[8];
    if ((tid & 31) == 0) { rs[tid >> 5] = s; rss[tid >> 5] = ss; }
    __syncthreads();
    if (tid == 0) {
        float S = 0.f, SS = 0.f;
#pragma unroll
        for (int i = 0; i < 8; ++i) { S += rs[i]; SS += rss[i]; }
        const float invN = 1.0f / (float)(Bn * Tdim);
        float mean = S * invN;
        float var  = SS * invN - mean * mean;
        float sc   = gamma[c] * rsqrtf(var + EPSV);
        s_out[c] = sc;
        t_out[c] = beta[c] - mean * sc;
    }
}

// ---------------------------------------------------------------------------
// Fold BN into weights: wf[o,c] = w[o,c]*s[c];  bf[o] = bias[o] + sum_c w[o,c]*t[c]
// grid = M blocks (one output channel each), 256 threads.
// ---------------------------------------------------------------------------
__global__ void fold_kernel(const float* __restrict__ w,
                            const float* __restrict__ bias_in,
                            const float* __restrict__ s,
                            const float* __restrict__ t,
                            float* __restrict__ wf,
                            float* __restrict__ bf,
                            int K)
{
    const int o = blockIdx.x, tid = threadIdx.x;
    float part = 0.f;
    for (int c = tid; c < K; c += 256) {
        float wv = w[(size_t)o * K + c];
        wf[(size_t)o * K + c] = wv * s[c];
        part += wv * t[c];
    }
#pragma unroll
    for (int off = 16; off > 0; off >>= 1)
        part += __shfl_xor_sync(0xffffffffu, part, off);
    __shared__ float red[8];
    if ((tid & 31) == 0) red[tid >> 5] = part;
    __syncthreads();
    if (tid == 0) {
        float tot = 0.f;
#pragma unroll
        for (int i = 0; i < 8; ++i) tot += red[i];
        bf[o] = bias_in[o] + tot;
    }
}

// ---------------------------------------------------------------------------
// tf32 GEMM:  Out(row o, col t) = sum_k A[o,k] * X[b,k,t]  (+ bias, epilogue)
// Block tile BM x 128, BK=16, 8 warps (2x4), warp tile (BM/2) x 32.
// mma.sync m16n8k8.  A staged k-major in SMEM (conflict-free frag loads).
// EPI=0: relu, write h[b][o][t].  EPI=1: bias, scatter mu/logvar.
// ---------------------------------------------------------------------------
template <int BM, int MT, int EPI>
__global__ __launch_bounds__(256)
void gemm_tf32_kernel(const float* __restrict__ A,
                      const float* __restrict__ X,
                      const float* __restrict__ bias,
                      float* __restrict__ Out,
                      int K, int Mtot)
{
    constexpr int NT  = 4;
    constexpr int AP  = BM + 4;
    constexpr int BP  = BN + 4;
    constexpr int AF4 = (BM * BK) / (4 * 256);

    __shared__ float As[2][BK][AP];   // k-major: As[k][m]
    __shared__ float Bs[2][BK][BP];   // Bs[k][n]

    const int tid  = threadIdx.x;
    const int wid  = tid >> 5, lane = tid & 31;
    const int wrow = wid >> 2, wcol = wid & 3;      // 2 x 4 warp grid
    const int gid  = lane >> 2, tig = lane & 3;

    const int b  = blockIdx.z;
    const int t0 = blockIdx.x * BN;
    const int m0 = blockIdx.y * BM;

    const float* Xb = X + (size_t)b * K * Tdim;

    float acc[MT][NT][4];
#pragma unroll
    for (int i = 0; i < MT; ++i)
#pragma unroll
        for (int j = 0; j < NT; ++j)
#pragma unroll
            for (int e = 0; e < 4; ++e) acc[i][j][e] = 0.f;

    // global->smem mapping
    int ar[AF4], aj[AF4];
#pragma unroll
    for (int i = 0; i < AF4; ++i) {
        int id = tid + i * 256;
        ar[i] = id >> 2;          // row in A tile
        aj[i] = (id & 3) * 4;     // k offset (float4)
    }
    const int bkb = tid >> 5;           // B tile k row (then +8 for second)
    const int bnn = (lane) * 4;         // 32 lanes * 4 floats = full 128 row

    // ---- prologue: tile 0 ----
    {
#pragma unroll
        for (int i = 0; i < AF4; ++i) {
            float4 v = *reinterpret_cast<const float4*>(A + (size_t)(m0 + ar[i]) * K + aj[i]);
            As[0][aj[i] + 0][ar[i]] = to_tf32(v.x);
            As[0][aj[i] + 1][ar[i]] = to_tf32(v.y);
            As[0][aj[i] + 2][ar[i]] = to_tf32(v.z);
            As[0][aj[i] + 3][ar[i]] = to_tf32(v.w);
        }
#pragma unroll
        for (int i = 0; i < 2; ++i) {
            int k = bkb + i * 8;
            float4 v = *reinterpret_cast<const float4*>(Xb + (size_t)k * Tdim + t0 + bnn);
            float4 c4 = make_float4(to_tf32(v.x), to_tf32(v.y), to_tf32(v.z), to_tf32(v.w));
            *reinterpret_cast<float4*>(&Bs[0][k][bnn]) = c4;
        }
    }
    __syncthreads();

    const int KT = K / BK;
    float4 a_reg[AF4], b_reg[2];

    for (int kt = 0; kt < KT; ++kt) {
        const int cur = kt & 1;
        const bool has_next = (kt + 1 < KT);
        if (has_next) {
            const int k0 = (kt + 1) * BK;
#pragma unroll
            for (int i = 0; i < AF4; ++i)
                a_reg[i] = *reinterpret_cast<const float4*>(
                    A + (size_t)(m0 + ar[i]) * K + k0 + aj[i]);
#pragma unroll
            for (int i = 0; i < 2; ++i) {
                int k = bkb + i * 8;
                b_reg[i] = *reinterpret_cast<const float4*>(
                    Xb + (size_t)(k0 + k) * Tdim + t0 + bnn);
            }
        }

#pragma unroll
        for (int kc = 0; kc < 2; ++kc) {
            const int kk = kc * 8 + tig;
            uint32_t af[MT][4], bfr[NT][2];
#pragma unroll
            for (int mt = 0; mt < MT; ++mt) {
                const int r = wrow * (BM / 2) + mt * 16 + gid;
                af[mt][0] = __float_as_uint(As[cur][kk    ][r]);
                af[mt][1] = __float_as_uint(As[cur][kk    ][r + 8]);
                af[mt][2] = __float_as_uint(As[cur][kk + 4][r]);
                af[mt][3] = __float_as_uint(As[cur][kk + 4][r + 8]);
            }
#pragma unroll
            for (int nt = 0; nt < NT; ++nt) {
                const int cc = wcol * 32 + nt * 8 + gid;
                bfr[nt][0] = __float_as_uint(Bs[cur][kk    ][cc]);
                bfr[nt][1] = __float_as_uint(Bs[cur][kk + 4][cc]);
            }
#pragma unroll
            for (int mt = 0; mt < MT; ++mt)
#pragma unroll
                for (int nt = 0; nt < NT; ++nt)
                    mma8(acc[mt][nt], af[mt], bfr[nt]);
        }

        if (has_next) {
            const int nb = cur ^ 1;
#pragma unroll
            for (int i = 0; i < AF4; ++i) {
                As[nb][aj[i] + 0][ar[i]] = to_tf32(a_reg[i].x);
                As[nb][aj[i] + 1][ar[i]] = to_tf32(a_reg[i].y);
                As[nb][aj[i] + 2][ar[i]] = to_tf32(a_reg[i].z);
                As[nb][aj[i] + 3][ar[i]] = to_tf32(a_reg[i].w);
            }
#pragma unroll
            for (int i = 0; i < 2; ++i) {
                int k = bkb + i * 8;
                float4 c4 = make_float4(to_tf32(b_reg[i].x), to_tf32(b_reg[i].y),
                                        to_tf32(b_reg[i].z), to_tf32(b_reg[i].w));
                *reinterpret_cast<float4*>(&Bs[nb][k][bnn]) = c4;
            }
        }
        __syncthreads();
    }

    // ---- epilogue ----
#pragma unroll
    for (int mt = 0; mt < MT; ++mt) {
        const int row = m0 + wrow * (BM / 2) + mt * 16 + gid;
        const float bz0 = bias[row];
        const float bz1 = bias[row + 8];
#pragma unroll
        for (int nt = 0; nt < NT; ++nt) {
            const int col = t0 + wcol * 32 + nt * 8 + tig * 2;
            if constexpr (EPI == 0) {
                float* H = Out + ((size_t)b * Mtot + row) * Tdim + col;
                float2 v0 = make_float2(fmaxf(acc[mt][nt][0] + bz0, 0.f),
                                        fmaxf(acc[mt][nt][1] + bz0, 0.f));
                float2 v1 = make_float2(fmaxf(acc[mt][nt][2] + bz1, 0.f),
                                        fmaxf(acc[mt][nt][3] + bz1, 0.f));
                *reinterpret_cast<float2*>(H) = v0;
                *reinterpret_cast<float2*>(H + (size_t)8 * Tdim) = v1;
            } else {
                // out[b, o, t] -> mu (o<32) then logvar (o>=32), each flattened
                const int row1 = row + 8;
                size_t i0 = (row < 32)
                    ? ((size_t)b * 65536 + (size_t)row * Tdim)
                    : (2097152 + (size_t)b * 65536 + (size_t)(row - 32) * Tdim);
                size_t i1 = (row1 < 32)
                    ? ((size_t)b * 65536 + (size_t)row1 * Tdim)
                    : (2097152 + (size_t)b * 65536 + (size_t)(row1 - 32) * Tdim);
                float2 v0 = make_float2(acc[mt][nt][0] + bz0, acc[mt][nt][1] + bz0);
                float2 v1 = make_float2(acc[mt][nt][2] + bz1, acc[mt][nt][3] + bz1);
                *reinterpret_cast<float2*>(Out + i0 + col) = v0;
                *reinterpret_cast<float2*>(Out + i1 + col) = v1;
            }
        }
    }
}

// ---------------------------------------------------------------------------
extern "C" void kernel_launch(void* const* d_in, const int* in_sizes, int n_in,
                              void* d_out, int out_size)
{
    const float* x     = (const float*)d_in[0];
    const float* bn1_g = (const float*)d_in[1];
    const float* bn1_b = (const float*)d_in[2];
    const float* w1    = (const float*)d_in[3];
    const float* b1    = (const float*)d_in[4];
    const float* bn2_g = (const float*)d_in[5];
    const float* bn2_b = (const float*)d_in[6];
    const float* w2    = (const float*)d_in[7];
    const float* b2    = (const float*)d_in[8];
    float* out = (float*)d_out;

    float *h, *s1, *t1, *w1f, *b1f, *s2, *t2, *w2f, *b2f;
    cudaGetSymbolAddress((void**)&h,   g_h);
    cudaGetSymbolAddress((void**)&s1,  g_s1);
    cudaGetSymbolAddress((void**)&t1,  g_t1);
    cudaGetSymbolAddress((void**)&w1f, g_w1f);
    cudaGetSymbolAddress((void**)&b1f, g_b1f);
    cudaGetSymbolAddress((void**)&s2,  g_s2);
    cudaGetSymbolAddress((void**)&t2,  g_t2);
    cudaGetSymbolAddress((void**)&w2f, g_w2f);
    cudaGetSymbolAddress((void**)&b2f, g_b2f);

    // BN1 stats -> fold into W1 -> GEMM1(relu) -> h
    bn_stats_kernel<<<1024, 256>>>(x, bn1_g, bn1_b, s1, t1, 1024);
    fold_kernel<<<256, 256>>>(w1, b1, s1, t1, w1f, b1f, 1024);
    gemm_tf32_kernel<128, 4, 0><<<dim3(16, 2, 32), 256>>>(w1f, x, b1f, h, 1024, 256);

    // BN2 stats on h -> fold into W2 -> GEMM2 with mu/logvar scatter
    bn_stats_kernel<<<256, 256>>>(h, bn2_g, bn2_b, s2, t2, 256);
    fold_kernel<<<64, 256>>>(w2, b2, s2, t2, w2f, b2f, 256);
    gemm_tf32_kernel<64, 2, 1><<<dim3(16, 1, 32), 256>>>(w2f, h, b2f, out, 256, 64);
}